// round 1
// baseline (speedup 1.0000x reference)
#include <cuda_runtime.h>
#include <math.h>

#define Bb 16
#define Ss 512
#define Dd 2048
#define Hh 16
#define HDd 128
#define Gg 4
#define GDd 512
#define MROWS (Bb*Ss)   // 8192

// Scratch (allocation-guard workaround: __device__ globals)
__device__ float g_Q[MROWS * Dd];    // 64 MB
__device__ float g_K[MROWS * GDd];   // 16 MB
__device__ float g_V[MROWS * GDd];   // 16 MB
__device__ float g_AO[MROWS * Dd];   // 64 MB

// ---------------------------------------------------------------------------
// SGEMM: C[M,N] = A[M,K] @ B[K,N] + bias[N].  M = gridDim.y*128.
// 128x128x8 tile, 256 threads, 8x8 microtile with stride-16 ownership.
// ---------------------------------------------------------------------------
__global__ __launch_bounds__(256) void sgemm_bias(
    const float* __restrict__ A, const float* __restrict__ Bm,
    const float* __restrict__ bias, float* __restrict__ C,
    int N, int K)
{
    __shared__ float As[8][128];
    __shared__ float Bs[8][128];
    const int t  = threadIdx.x;
    const int tx = t & 15, ty = t >> 4;
    const int m0 = blockIdx.y * 128, n0 = blockIdx.x * 128;

    const int arow = t >> 1, aseg = t & 1;      // A: 128 rows x 2 float4 segs
    const int brow = t >> 5, bseg = t & 31;     // B: 8 rows x 32 float4 segs
    const float* Aptr = A + (size_t)(m0 + arow) * K + aseg * 4;
    const float* Bptr = Bm + (size_t)brow * N + n0 + bseg * 4;

    float acc[8][8];
#pragma unroll
    for (int i = 0; i < 8; i++)
#pragma unroll
        for (int j = 0; j < 8; j++) acc[i][j] = 0.0f;

    for (int k0 = 0; k0 < K; k0 += 8) {
        float4 av = *(const float4*)(Aptr + k0);
        float4 bv = *(const float4*)(Bptr + (size_t)k0 * N);
        __syncthreads();
        As[aseg * 4 + 0][arow] = av.x;
        As[aseg * 4 + 1][arow] = av.y;
        As[aseg * 4 + 2][arow] = av.z;
        As[aseg * 4 + 3][arow] = av.w;
        *(float4*)&Bs[brow][bseg * 4] = bv;
        __syncthreads();
#pragma unroll
        for (int kk = 0; kk < 8; kk++) {
            float a[8], b[8];
#pragma unroll
            for (int i = 0; i < 8; i++) a[i] = As[kk][ty + 16 * i];
#pragma unroll
            for (int j = 0; j < 8; j++) b[j] = Bs[kk][tx + 16 * j];
#pragma unroll
            for (int i = 0; i < 8; i++)
#pragma unroll
                for (int j = 0; j < 8; j++) acc[i][j] = fmaf(a[i], b[j], acc[i][j]);
        }
    }

    float bv8[8];
#pragma unroll
    for (int j = 0; j < 8; j++) bv8[j] = bias[n0 + tx + 16 * j];
#pragma unroll
    for (int i = 0; i < 8; i++) {
        const size_t row = (size_t)(m0 + ty + 16 * i) * N + n0;
#pragma unroll
        for (int j = 0; j < 8; j++)
            C[row + tx + 16 * j] = acc[i][j] + bv8[j];
    }
}

// ---------------------------------------------------------------------------
// RMSNorm + RoPE postprocess. One warp per head-row of 128 floats.
// q rows also get the combined 1/hd (= inv_sqrt_hd applied twice) factor.
// ---------------------------------------------------------------------------
__global__ __launch_bounds__(256) void qk_post(const float* __restrict__ qscale,
                                               const float* __restrict__ kscale)
{
    const int warp = (blockIdx.x << 3) + (threadIdx.x >> 5);
    const int lane = threadIdx.x & 31;
    const int QROWS = Bb * Ss * Hh;

    float* ptr; int tpos; const float* scale; float extra;
    if (warp < QROWS) {
        int bs = warp / Hh, h = warp % Hh;
        ptr = g_Q + (size_t)bs * Dd + h * HDd;
        tpos = bs % Ss; scale = qscale; extra = 1.0f / 128.0f;
    } else {
        int w2 = warp - QROWS;
        int bs = w2 / Gg, g = w2 % Gg;
        ptr = g_K + (size_t)bs * GDd + g * HDd;
        tpos = bs % Ss; scale = kscale; extra = 1.0f;
    }

    float4 v  = ((const float4*)ptr)[lane];
    float4 sc = ((const float4*)scale)[lane];

    float ss = v.x*v.x + v.y*v.y + v.z*v.z + v.w*v.w;
#pragma unroll
    for (int o = 16; o; o >>= 1) ss += __shfl_xor_sync(0xFFFFFFFFu, ss, o);
    const float r = rsqrtf(ss * (1.0f / HDd) + 1e-6f);
    v.x *= r * sc.x; v.y *= r * sc.y; v.z *= r * sc.z; v.w *= r * sc.w;

    // RoPE: pairs (4l,4l+1) -> j0=2l ; (4l+2,4l+3) -> j1=2l+1
    const float FJ = -0.14391156831212787f;  // -ln(10000)/64
    const float tp = (float)tpos;
    const int j0 = 2 * lane, j1 = 2 * lane + 1;
    float s0, c0, s1, c1;
    sincosf(tp * expf(j0 * FJ), &s0, &c0);
    sincosf(tp * expf(j1 * FJ), &s1, &c1);

    float4 o;
    o.x = (v.x * c0 - v.y * s0) * extra;
    o.y = (v.x * s0 + v.y * c0) * extra;
    o.z = (v.z * c1 - v.w * s1) * extra;
    o.w = (v.z * s1 + v.w * c1) * extra;
    ((float4*)ptr)[lane] = o;
}

// ---------------------------------------------------------------------------
// Causal attention: block = (m-tile of 64 queries, head h, batch b).
// Full-row scores in smem (64 x 512) -> exact softmax, then PV.
// ---------------------------------------------------------------------------
#define QS_STRIDE 132
#define KV_STRIDE 133
#define SS_STRIDE 516
#define ATTN_SMEM (64 * (QS_STRIDE + KV_STRIDE + SS_STRIDE + 1) * 4)

extern __shared__ float sm_attn[];

__global__ __launch_bounds__(256) void attn_kernel()
{
    float* Qs  = sm_attn;
    float* KV  = Qs + 64 * QS_STRIDE;
    float* Ssm = KV + 64 * KV_STRIDE;
    float* inv = Ssm + 64 * SS_STRIDE;

    const int mi = blockIdx.x, h = blockIdx.y, b = blockIdx.z;
    const int g  = h >> 2;
    const int t  = threadIdx.x;
    const int tx = t & 15, ty = t >> 4;
    const int lane = t & 31, warp = t >> 5;
    const int m0 = mi * 64;
    const int ntiles = mi + 1;

    // Load Q tile (row-major, float4, stride 132)
    const float* Qg = g_Q + (size_t)(b * Ss + m0) * Dd + h * HDd;
    for (int idx = t; idx < 64 * 32; idx += 256) {
        int rr = idx >> 5, c4 = idx & 31;
        float4 v = *(const float4*)(Qg + (size_t)rr * Dd + c4 * 4);
        *(float4*)&Qs[rr * QS_STRIDE + c4 * 4] = v;
    }

    // ---- S = Q K^T (scaled+masked) per key tile ----
    for (int nt = 0; nt < ntiles; nt++) {
        __syncthreads();
        const float* Kg = g_K + (size_t)(b * Ss + nt * 64) * GDd + g * HDd;
        for (int idx = t; idx < 64 * 32; idx += 256) {
            int rr = idx >> 5, c4 = idx & 31;
            float4 v = *(const float4*)(Kg + (size_t)rr * GDd + c4 * 4);
            float* dptr = &KV[rr * KV_STRIDE + c4 * 4];
            dptr[0] = v.x; dptr[1] = v.y; dptr[2] = v.z; dptr[3] = v.w;
        }
        __syncthreads();

        float acc[4][4];
#pragma unroll
        for (int i = 0; i < 4; i++)
#pragma unroll
            for (int j = 0; j < 4; j++) acc[i][j] = 0.0f;

        for (int kk = 0; kk < HDd; kk++) {
            float a[4], bb[4];
#pragma unroll
            for (int i = 0; i < 4; i++) a[i]  = Qs[(ty + 16 * i) * QS_STRIDE + kk];
#pragma unroll
            for (int j = 0; j < 4; j++) bb[j] = KV[(tx + 16 * j) * KV_STRIDE + kk];
#pragma unroll
            for (int i = 0; i < 4; i++)
#pragma unroll
                for (int j = 0; j < 4; j++) acc[i][j] = fmaf(a[i], bb[j], acc[i][j]);
        }

#pragma unroll
        for (int i = 0; i < 4; i++) {
            const int rr = ty + 16 * i;
            const int mq = m0 + rr;
#pragma unroll
            for (int j = 0; j < 4; j++) {
                const int tk = nt * 64 + tx + 16 * j;
                Ssm[rr * SS_STRIDE + tk] = (tk <= mq) ? acc[i][j] : -3.0e38f;
            }
        }
    }
    __syncthreads();

    // ---- softmax (full row; warp w owns rows 8w..8w+7) ----
    const int L = ntiles * 64;
    for (int rr8 = 0; rr8 < 8; rr8++) {
        const int rr = warp * 8 + rr8;
        float* row = &Ssm[rr * SS_STRIDE];
        float mx = -3.0e38f;
        for (int c = lane; c < L; c += 32) mx = fmaxf(mx, row[c]);
#pragma unroll
        for (int o = 16; o; o >>= 1) mx = fmaxf(mx, __shfl_xor_sync(0xFFFFFFFFu, mx, o));
        float sum = 0.0f;
        for (int c = lane; c < L; c += 32) {
            float e = expf(row[c] - mx);
            row[c] = e; sum += e;
        }
#pragma unroll
        for (int o = 16; o; o >>= 1) sum += __shfl_xor_sync(0xFFFFFFFFu, sum, o);
        if (lane == 0) inv[rr] = 1.0f / sum;
    }

    // ---- O = P V ----
    float acc2[4][8];
#pragma unroll
    for (int i = 0; i < 4; i++)
#pragma unroll
        for (int j = 0; j < 8; j++) acc2[i][j] = 0.0f;

    for (int nt = 0; nt < ntiles; nt++) {
        __syncthreads();
        const float* Vg = g_V + (size_t)(b * Ss + nt * 64) * GDd + g * HDd;
        for (int idx = t; idx < 64 * 32; idx += 256) {
            int rr = idx >> 5, c4 = idx & 31;
            float4 v = *(const float4*)(Vg + (size_t)rr * GDd + c4 * 4);
            float* dptr = &KV[rr * KV_STRIDE + c4 * 4];
            dptr[0] = v.x; dptr[1] = v.y; dptr[2] = v.z; dptr[3] = v.w;
        }
        __syncthreads();

        for (int kk = 0; kk < 64; kk++) {
            float sv[4], vv[8];
#pragma unroll
            for (int i = 0; i < 4; i++) sv[i] = Ssm[(ty + 16 * i) * SS_STRIDE + nt * 64 + kk];
#pragma unroll
            for (int j = 0; j < 8; j++) vv[j] = KV[kk * KV_STRIDE + tx + 16 * j];
#pragma unroll
            for (int i = 0; i < 4; i++)
#pragma unroll
                for (int j = 0; j < 8; j++) acc2[i][j] = fmaf(sv[i], vv[j], acc2[i][j]);
        }
    }

    float* Og = g_AO + (size_t)(b * Ss + m0) * Dd + h * HDd;
#pragma unroll
    for (int i = 0; i < 4; i++) {
        const int rr = ty + 16 * i;
        const float scl = inv[rr];
#pragma unroll
        for (int j = 0; j < 8; j++)
            Og[(size_t)rr * Dd + tx + 16 * j] = acc2[i][j] * scl;
    }
}

// ---------------------------------------------------------------------------
extern "C" void kernel_launch(void* const* d_in, const int* in_sizes, int n_in,
                              void* d_out, int out_size)
{
    const float* x   = (const float*)d_in[0];
    const float* Wq  = (const float*)d_in[1];
    const float* bq  = (const float*)d_in[2];
    const float* Wk  = (const float*)d_in[3];
    const float* bk  = (const float*)d_in[4];
    const float* Wv  = (const float*)d_in[5];
    const float* bv  = (const float*)d_in[6];
    const float* Wo  = (const float*)d_in[7];
    const float* bo  = (const float*)d_in[8];
    const float* qns = (const float*)d_in[9];
    const float* kns = (const float*)d_in[10];
    float* out = (float*)d_out;

    float *gq, *gk, *gv, *gao;
    cudaGetSymbolAddress((void**)&gq,  g_Q);
    cudaGetSymbolAddress((void**)&gk,  g_K);
    cudaGetSymbolAddress((void**)&gv,  g_V);
    cudaGetSymbolAddress((void**)&gao, g_AO);

    cudaFuncSetAttribute(attn_kernel, cudaFuncAttributeMaxDynamicSharedMemorySize,
                         ATTN_SMEM);

    dim3 gQ(Dd / 128, MROWS / 128);    // 16 x 64
    dim3 gKV(GDd / 128, MROWS / 128);  //  4 x 64

    sgemm_bias<<<gQ, 256>>>(x, Wq, bq, gq, Dd, Dd);
    sgemm_bias<<<gKV, 256>>>(x, Wk, bk, gk, GDd, Dd);
    sgemm_bias<<<gKV, 256>>>(x, Wv, bv, gv, GDd, Dd);

    qk_post<<<(Bb * Ss * (Hh + Gg)) / 8, 256>>>(qns, kns);

    attn_kernel<<<dim3(8, Hh, Bb), 256, ATTN_SMEM>>>();

    sgemm_bias<<<gQ, 256>>>(gao, Wo, bo, out, Dd, Dd);
}

// round 3
// speedup vs baseline: 2.7419x; 2.7419x over previous
#include <cuda_runtime.h>
#include <cuda_bf16.h>
#include <math.h>
#include <stdint.h>

#define Bb 16
#define Ss 512
#define Dd 2048
#define Hh 16
#define HDd 128
#define Gg 4
#define GDd 512
#define MROWS (Bb*Ss)   // 8192

// ---------------- scratch (__device__ globals) ------------------------------
__device__ float g_Q[MROWS * Dd];
__device__ float g_K[MROWS * GDd];
__device__ float g_V[MROWS * GDd];
__device__ float g_AO[MROWS * Dd];

__device__ __align__(16) __nv_bfloat16 g_Xhi[MROWS * Dd];
__device__ __align__(16) __nv_bfloat16 g_Xlo[MROWS * Dd];
__device__ __align__(16) __nv_bfloat16 g_AOhi[MROWS * Dd];
__device__ __align__(16) __nv_bfloat16 g_AOlo[MROWS * Dd];

__device__ __align__(16) __nv_bfloat16 g_Wqt_hi[Dd * Dd];
__device__ __align__(16) __nv_bfloat16 g_Wqt_lo[Dd * Dd];
__device__ __align__(16) __nv_bfloat16 g_Wkt_hi[GDd * Dd];
__device__ __align__(16) __nv_bfloat16 g_Wkt_lo[GDd * Dd];
__device__ __align__(16) __nv_bfloat16 g_Wvt_hi[GDd * Dd];
__device__ __align__(16) __nv_bfloat16 g_Wvt_lo[GDd * Dd];
__device__ __align__(16) __nv_bfloat16 g_Wot_hi[Dd * Dd];
__device__ __align__(16) __nv_bfloat16 g_Wot_lo[Dd * Dd];

// ---------------- baseline-PTX helpers (NO 'a' features) --------------------
__device__ __forceinline__ uint32_t smem_u32(const void* p) {
    uint32_t a;
    asm("{ .reg .u64 t; cvta.to.shared.u64 t, %1; cvt.u32.u64 %0, t; }"
        : "=r"(a) : "l"(p));
    return a;
}
#define CP_ASYNC16(sm, g) \
    asm volatile("cp.async.cg.shared.global [%0], [%1], 16;" :: "r"(sm), "l"(g))
#define CP_COMMIT() asm volatile("cp.async.commit_group;" ::: "memory")
#define CP_WAIT1()  asm volatile("cp.async.wait_group 1;" ::: "memory")
#define CP_WAIT0()  asm volatile("cp.async.wait_group 0;" ::: "memory")

#define LDMATRIX_X4(r0, r1, r2, r3, addr) \
    asm volatile("ldmatrix.sync.aligned.m8n8.x4.shared.b16 {%0,%1,%2,%3}, [%4];" \
                 : "=r"(r0), "=r"(r1), "=r"(r2), "=r"(r3) : "r"(addr))

__device__ __forceinline__ void mma_bf16(float* c, const uint32_t* a, const uint32_t* b) {
    asm volatile("mma.sync.aligned.m16n8k16.row.col.f32.bf16.bf16.f32 "
                 "{%0,%1,%2,%3}, {%4,%5,%6,%7}, {%8,%9}, {%0,%1,%2,%3};"
                 : "+f"(c[0]), "+f"(c[1]), "+f"(c[2]), "+f"(c[3])
                 : "r"(a[0]), "r"(a[1]), "r"(a[2]), "r"(a[3]),
                   "r"(b[0]), "r"(b[1]));
}

// ---------------------------------------------------------------------------
// prep: elementwise fp32 -> bf16 hi/lo split
// ---------------------------------------------------------------------------
__global__ __launch_bounds__(256) void split_hilo(
    const float* __restrict__ src, __nv_bfloat16* __restrict__ hi,
    __nv_bfloat16* __restrict__ lo, int n4)
{
    int i = blockIdx.x * 256 + threadIdx.x;
    if (i >= n4) return;
    float4 v = ((const float4*)src)[i];
    __nv_bfloat16 h0 = __float2bfloat16_rn(v.x);
    __nv_bfloat16 h1 = __float2bfloat16_rn(v.y);
    __nv_bfloat16 h2 = __float2bfloat16_rn(v.z);
    __nv_bfloat16 h3 = __float2bfloat16_rn(v.w);
    __nv_bfloat16 l0 = __float2bfloat16_rn(v.x - __bfloat162float(h0));
    __nv_bfloat16 l1 = __float2bfloat16_rn(v.y - __bfloat162float(h1));
    __nv_bfloat16 l2 = __float2bfloat16_rn(v.z - __bfloat162float(h2));
    __nv_bfloat16 l3 = __float2bfloat16_rn(v.w - __bfloat162float(h3));
    __nv_bfloat162 hp0 = __nv_bfloat162(h0, h1), hp1 = __nv_bfloat162(h2, h3);
    __nv_bfloat162 lp0 = __nv_bfloat162(l0, l1), lp1 = __nv_bfloat162(l2, l3);
    ((uint2*)hi)[i] = make_uint2(*(uint32_t*)&hp0, *(uint32_t*)&hp1);
    ((uint2*)lo)[i] = make_uint2(*(uint32_t*)&lp0, *(uint32_t*)&lp1);
}

// ---------------------------------------------------------------------------
// prep: W[K,N] fp32 -> Wt[N,K] bf16 hi/lo (transpose + split)
// ---------------------------------------------------------------------------
__global__ __launch_bounds__(256) void transpose_split(
    const float* __restrict__ W, __nv_bfloat16* __restrict__ Thi,
    __nv_bfloat16* __restrict__ Tlo, int K, int N)
{
    __shared__ float ts[32][33];
    const int n0 = blockIdx.x * 32, k0 = blockIdx.y * 32;
    const int tx = threadIdx.x, ty = threadIdx.y;  // block (32, 8)
#pragma unroll
    for (int r = 0; r < 4; r++)
        ts[ty + 8 * r][tx] = W[(size_t)(k0 + ty + 8 * r) * N + n0 + tx];
    __syncthreads();
#pragma unroll
    for (int r = 0; r < 4; r++) {
        const int n = n0 + ty + 8 * r, k = k0 + tx;
        float v = ts[tx][ty + 8 * r];
        __nv_bfloat16 h = __float2bfloat16_rn(v);
        Thi[(size_t)n * K + k] = h;
        Tlo[(size_t)n * K + k] = __float2bfloat16_rn(v - __bfloat162float(h));
    }
}

// ---------------------------------------------------------------------------
// HMMA split-bf16 GEMM: C[M,N] = A[M,K] x B[N,K]^T + bias
// 128x128 tile, 8 warps (4x2), warp tile 32x64, mma.sync m16n8k16 bf16.
// K chunks of 64, cp.async double-buffered.
// smem layout per tile (128 rows x 64 bf16): byte = r*128 + (seg*16 ^ ((r&7)<<4))
// ---------------------------------------------------------------------------
#define GEMM_SMEM (2 * 65536)

extern __shared__ __align__(1024) char sm_gemm[];

__global__ __launch_bounds__(256, 1) void gemm_mma(
    const __nv_bfloat16* __restrict__ Ahi, const __nv_bfloat16* __restrict__ Alo,
    const __nv_bfloat16* __restrict__ Bhi, const __nv_bfloat16* __restrict__ Blo,
    const float* __restrict__ bias, float* __restrict__ C, int N, int K)
{
    const int t = threadIdx.x;
    const int warp = t >> 5, lane = t & 31;
    const int wm = warp & 3, wn = warp >> 2;  // 4 x 2 warp grid
    const int m0 = blockIdx.y * 128, n0 = blockIdx.x * 128;
    const uint32_t sbase = smem_u32(sm_gemm);

    const __nv_bfloat16* srcs[4] = {
        Ahi + (size_t)m0 * K, Alo + (size_t)m0 * K,
        Bhi + (size_t)n0 * K, Blo + (size_t)n0 * K };

    float acc[2][8][4];
#pragma unroll
    for (int mi = 0; mi < 2; mi++)
#pragma unroll
        for (int ni = 0; ni < 8; ni++)
#pragma unroll
            for (int q = 0; q < 4; q++) acc[mi][ni][q] = 0.0f;

    const int nchunks = K >> 6;  // 32

    // --- async copy of one k-chunk (64 cols) of all 4 tiles into stage s ---
    auto issue = [&](int i) {
        const uint32_t stg = sbase + (uint32_t)(i & 1) * 65536;
        const int k0 = i << 6;
#pragma unroll
        for (int it = 0; it < 16; it++) {
            int cid = t + it * 256;                  // 0..4095
            int tile = cid >> 10, r = (cid >> 3) & 127, seg = cid & 7;
            const __nv_bfloat16* g = srcs[tile] + (size_t)r * K + k0 + seg * 8;
            uint32_t sm = stg + tile * 16384 + r * 128 + ((seg * 16) ^ ((r & 7) << 4));
            CP_ASYNC16(sm, g);
        }
        CP_COMMIT();
    };

    // ldmatrix address precompute (per lane, stage-relative)
    // A frag (one 16-row m-tile, k-halves): lane -> row = rb + (lane&15), h = lane>>4
    const int a_r = lane & 15, a_h = lane >> 4;
    // B frag pair (two 8-row n-tiles): row = nb + p*16 + (lane>>4)*8 + (lane&7), half=(lane>>3)&1
    const int b_r = lane & 7, b_half = (lane >> 3) & 1, b_ts = lane >> 4;

    issue(0);

    for (int i = 0; i < nchunks; i++) {
        if (i + 1 < nchunks) { issue(i + 1); CP_WAIT1(); }
        else                 { CP_WAIT0(); }
        __syncthreads();

        const uint32_t stg = sbase + (uint32_t)(i & 1) * 65536;
        const uint32_t sAh = stg, sAl = stg + 16384, sBh = stg + 32768, sBl = stg + 49152;

#pragma unroll
        for (int ks = 0; ks < 4; ks++) {
            const uint32_t kb = ks * 32;
            uint32_t ah[2][4], al[2][4], bh[4][4], bl[4][4];
#pragma unroll
            for (int mi = 0; mi < 2; mi++) {
                const uint32_t row = wm * 32 + mi * 16 + a_r;
                const uint32_t off = row * 128 + ((kb + a_h * 16) ^ ((row & 7) << 4));
                LDMATRIX_X4(ah[mi][0], ah[mi][1], ah[mi][2], ah[mi][3], sAh + off);
                LDMATRIX_X4(al[mi][0], al[mi][1], al[mi][2], al[mi][3], sAl + off);
            }
#pragma unroll
            for (int p = 0; p < 4; p++) {
                const uint32_t row = wn * 64 + p * 16 + b_ts * 8 + b_r;
                const uint32_t off = row * 128 + ((kb + b_half * 16) ^ ((row & 7) << 4));
                LDMATRIX_X4(bh[p][0], bh[p][1], bh[p][2], bh[p][3], sBh + off);
                LDMATRIX_X4(bl[p][0], bl[p][1], bl[p][2], bl[p][3], sBl + off);
            }
#pragma unroll
            for (int mi = 0; mi < 2; mi++)
#pragma unroll
                for (int p = 0; p < 4; p++) {
                    mma_bf16(acc[mi][2 * p + 0], ah[mi], &bh[p][0]);
                    mma_bf16(acc[mi][2 * p + 1], ah[mi], &bh[p][2]);
                    mma_bf16(acc[mi][2 * p + 0], ah[mi], &bl[p][0]);
                    mma_bf16(acc[mi][2 * p + 1], ah[mi], &bl[p][2]);
                    mma_bf16(acc[mi][2 * p + 0], al[mi], &bh[p][0]);
                    mma_bf16(acc[mi][2 * p + 1], al[mi], &bh[p][2]);
                }
        }
        __syncthreads();
    }

    // ---- epilogue: bias + store ----
#pragma unroll
    for (int mi = 0; mi < 2; mi++) {
        const int row = m0 + wm * 32 + mi * 16 + (lane >> 2);
#pragma unroll
        for (int ni = 0; ni < 8; ni++) {
            const int col = n0 + wn * 64 + ni * 8 + (lane & 3) * 2;
            const float bx = bias[col], by = bias[col + 1];
            float* c = acc[mi][ni];
            float2 o0 = make_float2(c[0] + bx, c[1] + by);
            float2 o1 = make_float2(c[2] + bx, c[3] + by);
            *(float2*)&C[(size_t)row * N + col] = o0;
            *(float2*)&C[(size_t)(row + 8) * N + col] = o1;
        }
    }
}

// ---------------------------------------------------------------------------
// RMSNorm + RoPE postprocess (unchanged from passing R1)
// ---------------------------------------------------------------------------
__global__ __launch_bounds__(256) void qk_post(const float* __restrict__ qscale,
                                               const float* __restrict__ kscale)
{
    const int warp = (blockIdx.x << 3) + (threadIdx.x >> 5);
    const int lane = threadIdx.x & 31;
    const int QROWS = Bb * Ss * Hh;

    float* ptr; int tpos; const float* scale; float extra;
    if (warp < QROWS) {
        int bs = warp / Hh, h = warp % Hh;
        ptr = g_Q + (size_t)bs * Dd + h * HDd;
        tpos = bs % Ss; scale = qscale; extra = 1.0f / 128.0f;
    } else {
        int w2 = warp - QROWS;
        int bs = w2 / Gg, g = w2 % Gg;
        ptr = g_K + (size_t)bs * GDd + g * HDd;
        tpos = bs % Ss; scale = kscale; extra = 1.0f;
    }

    float4 v  = ((const float4*)ptr)[lane];
    float4 sc = ((const float4*)scale)[lane];

    float ss = v.x*v.x + v.y*v.y + v.z*v.z + v.w*v.w;
#pragma unroll
    for (int o = 16; o; o >>= 1) ss += __shfl_xor_sync(0xFFFFFFFFu, ss, o);
    const float r = rsqrtf(ss * (1.0f / HDd) + 1e-6f);
    v.x *= r * sc.x; v.y *= r * sc.y; v.z *= r * sc.z; v.w *= r * sc.w;

    const float FJ = -0.14391156831212787f;  // -ln(10000)/64
    const float tp = (float)tpos;
    const int j0 = 2 * lane, j1 = 2 * lane + 1;
    float s0, c0, s1, c1;
    sincosf(tp * expf(j0 * FJ), &s0, &c0);
    sincosf(tp * expf(j1 * FJ), &s1, &c1);

    float4 o;
    o.x = (v.x * c0 - v.y * s0) * extra;
    o.y = (v.x * s0 + v.y * c0) * extra;
    o.z = (v.z * c1 - v.w * s1) * extra;
    o.w = (v.z * s1 + v.w * c1) * extra;
    ((float4*)ptr)[lane] = o;
}

// ---------------------------------------------------------------------------
// Causal attention (unchanged fp32 path from passing R1)
// ---------------------------------------------------------------------------
#define QS_STRIDE 132
#define KV_STRIDE 133
#define SS_STRIDE 516
#define ATTN_SMEM (64 * (QS_STRIDE + KV_STRIDE + SS_STRIDE + 1) * 4)

extern __shared__ float sm_attn[];

__global__ __launch_bounds__(256) void attn_kernel()
{
    float* Qs  = sm_attn;
    float* KV  = Qs + 64 * QS_STRIDE;
    float* Ssm = KV + 64 * KV_STRIDE;
    float* inv = Ssm + 64 * SS_STRIDE;

    const int mi = blockIdx.x, h = blockIdx.y, b = blockIdx.z;
    const int g  = h >> 2;
    const int t  = threadIdx.x;
    const int tx = t & 15, ty = t >> 4;
    const int lane = t & 31, warp = t >> 5;
    const int m0 = mi * 64;
    const int ntiles = mi + 1;

    const float* Qg = g_Q + (size_t)(b * Ss + m0) * Dd + h * HDd;
    for (int idx = t; idx < 64 * 32; idx += 256) {
        int rr = idx >> 5, c4 = idx & 31;
        float4 v = *(const float4*)(Qg + (size_t)rr * Dd + c4 * 4);
        *(float4*)&Qs[rr * QS_STRIDE + c4 * 4] = v;
    }

    for (int nt = 0; nt < ntiles; nt++) {
        __syncthreads();
        const float* Kg = g_K + (size_t)(b * Ss + nt * 64) * GDd + g * HDd;
        for (int idx = t; idx < 64 * 32; idx += 256) {
            int rr = idx >> 5, c4 = idx & 31;
            float4 v = *(const float4*)(Kg + (size_t)rr * GDd + c4 * 4);
            float* dptr = &KV[rr * KV_STRIDE + c4 * 4];
            dptr[0] = v.x; dptr[1] = v.y; dptr[2] = v.z; dptr[3] = v.w;
        }
        __syncthreads();

        float acc[4][4];
#pragma unroll
        for (int i = 0; i < 4; i++)
#pragma unroll
            for (int j = 0; j < 4; j++) acc[i][j] = 0.0f;

        for (int kk = 0; kk < HDd; kk++) {
            float a[4], bb[4];
#pragma unroll
            for (int i = 0; i < 4; i++) a[i]  = Qs[(ty + 16 * i) * QS_STRIDE + kk];
#pragma unroll
            for (int j = 0; j < 4; j++) bb[j] = KV[(tx + 16 * j) * KV_STRIDE + kk];
#pragma unroll
            for (int i = 0; i < 4; i++)
#pragma unroll
                for (int j = 0; j < 4; j++) acc[i][j] = fmaf(a[i], bb[j], acc[i][j]);
        }

#pragma unroll
        for (int i = 0; i < 4; i++) {
            const int rr = ty + 16 * i;
            const int mq = m0 + rr;
#pragma unroll
            for (int j = 0; j < 4; j++) {
                const int tk = nt * 64 + tx + 16 * j;
                Ssm[rr * SS_STRIDE + tk] = (tk <= mq) ? acc[i][j] : -3.0e38f;
            }
        }
    }
    __syncthreads();

    const int L = ntiles * 64;
    for (int rr8 = 0; rr8 < 8; rr8++) {
        const int rr = warp * 8 + rr8;
        float* row = &Ssm[rr * SS_STRIDE];
        float mx = -3.0e38f;
        for (int c = lane; c < L; c += 32) mx = fmaxf(mx, row[c]);
#pragma unroll
        for (int o = 16; o; o >>= 1) mx = fmaxf(mx, __shfl_xor_sync(0xFFFFFFFFu, mx, o));
        float sum = 0.0f;
        for (int c = lane; c < L; c += 32) {
            float e = expf(row[c] - mx);
            row[c] = e; sum += e;
        }
#pragma unroll
        for (int o = 16; o; o >>= 1) sum += __shfl_xor_sync(0xFFFFFFFFu, sum, o);
        if (lane == 0) inv[rr] = 1.0f / sum;
    }

    float acc2[4][8];
#pragma unroll
    for (int i = 0; i < 4; i++)
#pragma unroll
        for (int j = 0; j < 8; j++) acc2[i][j] = 0.0f;

    for (int nt = 0; nt < ntiles; nt++) {
        __syncthreads();
        const float* Vg = g_V + (size_t)(b * Ss + nt * 64) * GDd + g * HDd;
        for (int idx = t; idx < 64 * 32; idx += 256) {
            int rr = idx >> 5, c4 = idx & 31;
            float4 v = *(const float4*)(Vg + (size_t)rr * GDd + c4 * 4);
            float* dptr = &KV[rr * KV_STRIDE + c4 * 4];
            dptr[0] = v.x; dptr[1] = v.y; dptr[2] = v.z; dptr[3] = v.w;
        }
        __syncthreads();

        for (int kk = 0; kk < 64; kk++) {
            float sv[4], vv[8];
#pragma unroll
            for (int i = 0; i < 4; i++) sv[i] = Ssm[(ty + 16 * i) * SS_STRIDE + nt * 64 + kk];
#pragma unroll
            for (int j = 0; j < 8; j++) vv[j] = KV[kk * KV_STRIDE + tx + 16 * j];
#pragma unroll
            for (int i = 0; i < 4; i++)
#pragma unroll
                for (int j = 0; j < 8; j++) acc2[i][j] = fmaf(sv[i], vv[j], acc2[i][j]);
        }
    }

    float* Og = g_AO + (size_t)(b * Ss + m0) * Dd + h * HDd;
#pragma unroll
    for (int i = 0; i < 4; i++) {
        const int rr = ty + 16 * i;
        const float scl = inv[rr];
#pragma unroll
        for (int j = 0; j < 8; j++)
            Og[(size_t)rr * Dd + tx + 16 * j] = acc2[i][j] * scl;
    }
}

// ---------------------------------------------------------------------------
extern "C" void kernel_launch(void* const* d_in, const int* in_sizes, int n_in,
                              void* d_out, int out_size)
{
    const float* x   = (const float*)d_in[0];
    const float* Wq  = (const float*)d_in[1];
    const float* bq  = (const float*)d_in[2];
    const float* Wk  = (const float*)d_in[3];
    const float* bk  = (const float*)d_in[4];
    const float* Wv  = (const float*)d_in[5];
    const float* bv  = (const float*)d_in[6];
    const float* Wo  = (const float*)d_in[7];
    const float* bo  = (const float*)d_in[8];
    const float* qns = (const float*)d_in[9];
    const float* kns = (const float*)d_in[10];
    float* out = (float*)d_out;

    float *gq, *gk, *gv, *gao;
    __nv_bfloat16 *xhi, *xlo, *aohi, *aolo;
    __nv_bfloat16 *wqh, *wql, *wkh, *wkl, *wvh, *wvl, *woh, *wol;
    cudaGetSymbolAddress((void**)&gq,  g_Q);
    cudaGetSymbolAddress((void**)&gk,  g_K);
    cudaGetSymbolAddress((void**)&gv,  g_V);
    cudaGetSymbolAddress((void**)&gao, g_AO);
    cudaGetSymbolAddress((void**)&xhi,  g_Xhi);
    cudaGetSymbolAddress((void**)&xlo,  g_Xlo);
    cudaGetSymbolAddress((void**)&aohi, g_AOhi);
    cudaGetSymbolAddress((void**)&aolo, g_AOlo);
    cudaGetSymbolAddress((void**)&wqh, g_Wqt_hi);
    cudaGetSymbolAddress((void**)&wql, g_Wqt_lo);
    cudaGetSymbolAddress((void**)&wkh, g_Wkt_hi);
    cudaGetSymbolAddress((void**)&wkl, g_Wkt_lo);
    cudaGetSymbolAddress((void**)&wvh, g_Wvt_hi);
    cudaGetSymbolAddress((void**)&wvl, g_Wvt_lo);
    cudaGetSymbolAddress((void**)&woh, g_Wot_hi);
    cudaGetSymbolAddress((void**)&wol, g_Wot_lo);

    cudaFuncSetAttribute(attn_kernel, cudaFuncAttributeMaxDynamicSharedMemorySize, ATTN_SMEM);
    cudaFuncSetAttribute(gemm_mma, cudaFuncAttributeMaxDynamicSharedMemorySize, GEMM_SMEM);

    // ---- prep: splits + weight transposes ----
    const int n4x = MROWS * Dd / 4;
    split_hilo<<<(n4x + 255) / 256, 256>>>(x, xhi, xlo, n4x);
    dim3 tb(32, 8);
    transpose_split<<<dim3(Dd / 32, Dd / 32), tb>>>(Wq, wqh, wql, Dd, Dd);
    transpose_split<<<dim3(GDd / 32, Dd / 32), tb>>>(Wk, wkh, wkl, Dd, GDd);
    transpose_split<<<dim3(GDd / 32, Dd / 32), tb>>>(Wv, wvh, wvl, Dd, GDd);
    transpose_split<<<dim3(Dd / 32, Dd / 32), tb>>>(Wo, woh, wol, Dd, Dd);

    // ---- projections (HMMA) ----
    gemm_mma<<<dim3(Dd / 128, MROWS / 128), 256, GEMM_SMEM>>>(xhi, xlo, wqh, wql, bq, gq, Dd, Dd);
    gemm_mma<<<dim3(GDd / 128, MROWS / 128), 256, GEMM_SMEM>>>(xhi, xlo, wkh, wkl, bk, gk, GDd, Dd);
    gemm_mma<<<dim3(GDd / 128, MROWS / 128), 256, GEMM_SMEM>>>(xhi, xlo, wvh, wvl, bv, gv, GDd, Dd);

    qk_post<<<(Bb * Ss * (Hh + Gg)) / 8, 256>>>(qns, kns);

    attn_kernel<<<dim3(8, Hh, Bb), 256, ATTN_SMEM>>>();

    // ---- output projection ----
    split_hilo<<<(n4x + 255) / 256, 256>>>(gao, aohi, aolo, n4x);
    gemm_mma<<<dim3(Dd / 128, MROWS / 128), 256, GEMM_SMEM>>>(aohi, aolo, woh, wol, bo, out, Dd, Dd);
}